// round 10
// baseline (speedup 1.0000x reference)
#include <cuda_runtime.h>
#include <cuda_bf16.h>

#define START_ID 62
#define PAD_ID   63
#define BATCH    512
#define SEQ      512
#define LBL      64
#define OV       12
#define SEGS     8
#define SEGW     64

typedef unsigned long long ull;

__device__ __forceinline__ float ex2f_(float x) {
    float y; asm("ex2.approx.f32 %0, %1;" : "=f"(y) : "f"(x)); return y;
}
__device__ __forceinline__ float lg2f_(float x) {
    float y; asm("lg2.approx.f32 %0, %1;" : "=f"(y) : "f"(x)); return y;
}
__device__ __forceinline__ ull fma2_(ull a, ull b, ull c) {
    ull d; asm("fma.rn.f32x2 %0, %1, %2, %3;" : "=l"(d) : "l"(a), "l"(b), "l"(c)); return d;
}
__device__ __forceinline__ ull add2_(ull a, ull b) {
    ull d; asm("add.rn.f32x2 %0, %1, %2;" : "=l"(d) : "l"(a), "l"(b)); return d;
}
__device__ __forceinline__ ull pack2_(float lo, float hi) {
    ull d; asm("mov.b64 %0, {%1, %2};" : "=l"(d) : "f"(lo), "f"(hi)); return d;
}
__device__ __forceinline__ void unpack2_(ull v, float& lo, float& hi) {
    asm("mov.b64 {%0, %1}, %2;" : "=f"(lo), "=f"(hi) : "l"(v));
}

// Fixed-time segmentation (seg k = times [64k,64k+64)), 2 BATCHES PER WARP
// sharing the same E register set (E depends on lane only). Batch with the
// shorter active range is frozen by predicated SELs — exact. Segment k>0
// restarts at 64k-OV (Birkhoff burn-in); telescoping V-terms cancel shifts.
__global__ __launch_bounds__(128, 2) void crf_loss_kernel(
    const float* __restrict__ ts,          // [B, S, L]
    const float* __restrict__ Tm,          // [L, L]
    const void*  __restrict__ labels_raw,  // [B, S] int32 or int64
    const void*  __restrict__ lengths_raw, // [B]    int32 or int64
    float* __restrict__ out)
{
    const int w   = threadIdx.x >> 5;
    const int tid = threadIdx.x & 31;            // lane: labels 2*tid, 2*tid+1
    const int seg = blockIdx.x >> 6;             // 8 segs x 64 blocks
    const int b0  = ((blockIdx.x & 63) << 3) + (w << 1);
    const int b1  = b0 + 1;
    const unsigned FULL = 0xffffffffu;

    __shared__ __align__(16) float sp[4][2][2][LBL]; // [warp][buf][batch][label]

    const float INV_LN2 = 1.44269504088896340736f;
    const float LN2     = 0.69314718055994530942f;

    // dtype detect: lengths viewed as int32 — word[1]==0 iff data is int64
    const int* l32 = (const int*)lengths_raw;
    const bool is64 = (l32[1] == 0);
    int len0, len1;
    if (is64) {
        len0 = (int)(((const long long*)lengths_raw)[b0]);
        len1 = (int)(((const long long*)lengths_raw)[b1]);
    } else { len0 = l32[b0]; len1 = l32[b1]; }

    const int  tauB = seg * SEGW;
    const int  tauE = tauB + SEGW;
    const bool act0 = (seg == 0) || (len0 > tauB);
    const bool act1 = (seg == 0) || (len1 > tauB);
    if (!act0 && !act1) return;
    const bool last0 = act0 && (len0 <= tauE);
    const bool last1 = act1 && (len1 <= tauE);

    const float* tsb0 = ts + (size_t)b0 * SEQ * LBL;
    const float* tsb1 = ts + (size_t)b1 * SEQ * LBL;
    const float2* t20 = (const float2*)tsb0;
    const float2* t21 = (const float2*)tsb1;

    // ---- E = exp(T) packed along i-pairs (shared by both batches) ----
    ull EA[32], EB[32];
    {
        const float2* Tm2 = (const float2*)Tm;
        #pragma unroll
        for (int q = 0; q < 32; ++q) {
            float2 r0 = Tm2[(2*q)     * 32 + tid];
            float2 r1 = Tm2[(2*q + 1) * 32 + tid];
            EA[q] = pack2_(__expf(r0.x), __expf(r1.x));
            EB[q] = pack2_(__expf(r0.y), __expf(r1.y));
        }
    }

    const int s0 = (seg == 0) ? 0 : (tauB - OV);
    const int e0 = act0 ? (last0 ? len0 - 1 : tauE) : s0;
    const int e1 = act1 ? (last1 ? len1 - 1 : tauE) : s0;
    const int n0 = e0 - s0, n1 = e1 - s0;
    const int nmax = (n0 > n1) ? n0 : n1;
    const int urec = (seg > 0) ? OV : -1;

    // ---- init A at s0 per batch ----
    float2 i0 = t20[(size_t)s0 * 32 + tid];
    float2 i1 = t21[(size_t)s0 * 32 + tid];
    float A00, A01, A10, A11;
    if (seg == 0) {
        float2 tv = ((const float2*)(Tm + START_ID * LBL))[tid];
        A00 = (i0.x + tv.x) * INV_LN2; A01 = (i0.y + tv.y) * INV_LN2;
        A10 = (i1.x + tv.x) * INV_LN2; A11 = (i1.y + tv.y) * INV_LN2;
    } else {
        A00 = i0.x * INV_LN2; A01 = i0.y * INV_LN2;
        A10 = i1.x * INV_LN2; A11 = i1.y * INV_LN2;
    }
    float M0 = __shfl_sync(FULL, A00, 0);
    float M1 = __shfl_sync(FULL, A10, 0);
    float Px0 = ex2f_(A00 - M0), Py0 = ex2f_(A01 - M0);
    float Px1 = ex2f_(A10 - M1), Py1 = ex2f_(A11 - M1);
    ((float2*)sp[w][0][0])[tid] = make_float2(Px0, Py0);
    ((float2*)sp[w][0][1])[tid] = make_float2(Px1, Py1);

    float Ms0 = M0, Ps0 = Px0, Ms1 = M1, Ps1 = Px1;

    // ---- emission prefetch rings, 4 deep, raw, clamped ----
    float2 er0[4], er1[4];
    #pragma unroll
    for (int kk = 0; kk < 4; ++kk) {
        int u0 = s0 + 1 + kk; if (u0 > e0) u0 = e0;
        int u1 = s0 + 1 + kk; if (u1 > e1) u1 = e1;
        er0[kk] = t20[(size_t)u0 * 32 + tid];
        er1[kk] = t21[(size_t)u1 * 32 + tid];
    }

    int buf = 0;

    #pragma unroll 8
    for (int u = 1; u <= nmax; ++u) {
        const int slot = (u - 1) & 3;
        float ex0 = er0[slot].x, ey0 = er0[slot].y;
        float ex1 = er1[slot].x, ey1 = er1[slot].y;
        {
            int t0 = s0 + u + 4; if (t0 > e0) t0 = e0;
            int t1 = s0 + u + 4; if (t1 > e1) t1 = e1;
            er0[slot] = t20[(size_t)t0 * 32 + tid];
            er1[slot] = t21[(size_t)t1 * 32 + tid];
        }
        const bool g0 = (u <= n0), g1 = (u <= n1);

        float c00, c01, c10, c11;
        if ((u & 7) == 1) {   // renorm step (compile-time under unroll 8)
            float p00 = __shfl_sync(FULL, Px0, 0);
            float p10 = __shfl_sync(FULL, Px1, 0);
            float Kp0 = lg2f_(p00), Kp1 = lg2f_(p10);
            c00 = ex2f_(fmaf(ex0, INV_LN2, -Kp0));
            c01 = ex2f_(fmaf(ey0, INV_LN2, -Kp0));
            c10 = ex2f_(fmaf(ex1, INV_LN2, -Kp1));
            c11 = ex2f_(fmaf(ey1, INV_LN2, -Kp1));
            M0 += g0 ? Kp0 : 0.0f;
            M1 += g1 ? Kp1 : 0.0f;
        } else {
            c00 = ex2f_(ex0 * INV_LN2);
            c01 = ex2f_(ey0 * INV_LN2);
            c10 = ex2f_(ex1 * INV_LN2);
            c11 = ex2f_(ey1 * INV_LN2);
        }

        __syncwarp();

        // matvec for both batches against the SAME E registers
        const ulonglong2* p40 = (const ulonglong2*)sp[w][buf][0];
        const ulonglong2* p41 = (const ulonglong2*)sp[w][buf][1];
        ull qa0 = 0, qa1 = 0, qb0 = 0, qb1 = 0;
        ull ra0 = 0, ra1 = 0, rb0 = 0, rb1 = 0;
        #pragma unroll
        for (int q = 0; q < 16; ++q) {
            ulonglong2 v0 = p40[q];
            ulonglong2 v1 = p41[q];
            qa0 = fma2_(v0.x, EA[2*q],     qa0);
            qa1 = fma2_(v0.y, EA[2*q + 1], qa1);
            qb0 = fma2_(v0.x, EB[2*q],     qb0);
            qb1 = fma2_(v0.y, EB[2*q + 1], qb1);
            ra0 = fma2_(v1.x, EA[2*q],     ra0);
            ra1 = fma2_(v1.y, EA[2*q + 1], ra1);
            rb0 = fma2_(v1.x, EB[2*q],     rb0);
            rb1 = fma2_(v1.y, EB[2*q + 1], rb1);
        }
        float u0x, u0y, u1x, u1y, v0x, v0y, v1x, v1y;
        unpack2_(add2_(qa0, qa1), u0x, u0y);
        unpack2_(add2_(qb0, qb1), u1x, u1y);
        unpack2_(add2_(ra0, ra1), v0x, v0y);
        unpack2_(add2_(rb0, rb1), v1x, v1y);

        float nPx0 = (u0x + u0y) * c00;
        float nPy0 = (u1x + u1y) * c01;
        float nPx1 = (v0x + v0y) * c10;
        float nPy1 = (v1x + v1y) * c11;
        Px0 = g0 ? nPx0 : Px0;  Py0 = g0 ? nPy0 : Py0;
        Px1 = g1 ? nPx1 : Px1;  Py1 = g1 ? nPy1 : Py1;

        ((float2*)sp[w][buf ^ 1][0])[tid] = make_float2(Px0, Py0);
        ((float2*)sp[w][buf ^ 1][1])[tid] = make_float2(Px1, Py1);
        buf ^= 1;

        if (u == urec) { Ms0 = M0; Ps0 = Px0; Ms1 = M1; Ps1 = Px1; }
    }

    // ---- per-batch forward contribution (log2 units) ----
    float tp0 = Tm[(2*tid)     * LBL + PAD_ID] * INV_LN2;
    float tp1 = Tm[(2*tid + 1) * LBL + PAD_ID] * INV_LN2;

    float fwd = 0.0f;
    #pragma unroll
    for (int bb = 0; bb < 2; ++bb) {
        const bool act  = bb ? act1  : act0;
        const bool last = bb ? last1 : last0;
        if (!act) continue;
        float Mc = bb ? M1  : M0;
        float px = bb ? Px1 : Px0;
        float py = bb ? Py1 : Py0;
        float f;
        if (last) {
            float z0 = Mc + lg2f_(px) + tp0;
            float z1 = Mc + lg2f_(py) + tp1;
            float m = fmaxf(z0, z1);
            #pragma unroll
            for (int o = 16; o > 0; o >>= 1)
                m = fmaxf(m, __shfl_xor_sync(FULL, m, o));
            float sv = ex2f_(z0 - m) + ex2f_(z1 - m);
            #pragma unroll
            for (int o = 16; o > 0; o >>= 1)
                sv += __shfl_xor_sync(FULL, sv, o);
            f = m + lg2f_(sv);
        } else {
            float pe0 = __shfl_sync(FULL, px, 0);
            f = Mc + lg2f_(pe0);
        }
        if (seg > 0) {
            float ms = bb ? Ms1 : Ms0;
            float ps = __shfl_sync(FULL, bb ? Ps1 : Ps0, 0);
            f -= (ms + lg2f_(ps));
        }
        fwd += f;
    }

    // ---- gold path scores over [tauB, min(tauE, len)) for both batches ----
    float gsum = 0.0f;
    int ll0 = 0, ll1 = 0;
    if (is64) {
        const long long* la0 = (const long long*)labels_raw + (size_t)b0 * SEQ;
        const long long* la1 = (const long long*)labels_raw + (size_t)b1 * SEQ;
        int hi0 = last0 ? len0 : (act0 ? tauE : tauB);
        int hi1 = last1 ? len1 : (act1 ? tauE : tauB);
        for (int t = tauB + tid; t < hi0; t += 32) {
            int lt = (int)la0[t];
            int pt = (t == 0) ? START_ID : (int)la0[t - 1];
            gsum += Tm[pt * LBL + lt] + tsb0[(size_t)t * LBL + lt];
        }
        for (int t = tauB + tid; t < hi1; t += 32) {
            int lt = (int)la1[t];
            int pt = (t == 0) ? START_ID : (int)la1[t - 1];
            gsum += Tm[pt * LBL + lt] + tsb1[(size_t)t * LBL + lt];
        }
        if (tid == 0) {
            if (last0) ll0 = (int)la0[len0 - 1];
            if (last1) ll1 = (int)la1[len1 - 1];
        }
    } else {
        const int* la0 = (const int*)labels_raw + (size_t)b0 * SEQ;
        const int* la1 = (const int*)labels_raw + (size_t)b1 * SEQ;
        int hi0 = last0 ? len0 : (act0 ? tauE : tauB);
        int hi1 = last1 ? len1 : (act1 ? tauE : tauB);
        for (int t = tauB + tid; t < hi0; t += 32) {
            int lt = la0[t];
            int pt = (t == 0) ? START_ID : la0[t - 1];
            gsum += Tm[pt * LBL + lt] + tsb0[(size_t)t * LBL + lt];
        }
        for (int t = tauB + tid; t < hi1; t += 32) {
            int lt = la1[t];
            int pt = (t == 0) ? START_ID : la1[t - 1];
            gsum += Tm[pt * LBL + lt] + tsb1[(size_t)t * LBL + lt];
        }
        if (tid == 0) {
            if (last0) ll0 = (int)la0[len0 - 1];
            if (last1) ll1 = (int)la1[len1 - 1];
        }
    }
    #pragma unroll
    for (int o = 16; o > 0; o >>= 1)
        gsum += __shfl_xor_sync(FULL, gsum, o);

    if (tid == 0) {
        float gold = gsum;
        if (last0) gold += Tm[ll0 * LBL + PAD_ID];
        if (last1) gold += Tm[ll1 * LBL + PAD_ID];
        atomicAdd(out, (fwd * LN2 - gold) * (1.0f / (float)BATCH));
    }
}

extern "C" void kernel_launch(void* const* d_in, const int* in_sizes, int n_in,
                              void* d_out, int out_size)
{
    const float* ts      = (const float*)d_in[0];
    const float* Tm      = (const float*)d_in[1];
    const void*  labels  = d_in[2];
    const void*  lengths = d_in[3];
    float* out = (float*)d_out;

    cudaMemsetAsync(out, 0, sizeof(float));
    crf_loss_kernel<<<SEGS * (BATCH / 8), 128>>>(ts, Tm, labels, lengths, out);
}

// round 11
// speedup vs baseline: 1.2260x; 1.2260x over previous
#include <cuda_runtime.h>
#include <cuda_bf16.h>

#define START_ID 62
#define PAD_ID   63
#define BATCH    512
#define SEQ      512
#define LBL      64
#define SEGS     8
#define SEGW     64
#define NSEG     80   // steps per non-first segment (incl. burn-in)

typedef unsigned long long ull;

__device__ __forceinline__ float ex2f_(float x) {
    float y; asm("ex2.approx.f32 %0, %1;" : "=f"(y) : "f"(x)); return y;
}
__device__ __forceinline__ float lg2f_(float x) {
    float y; asm("lg2.approx.f32 %0, %1;" : "=f"(y) : "f"(x)); return y;
}
__device__ __forceinline__ ull fma2_(ull a, ull b, ull c) {
    ull d; asm("fma.rn.f32x2 %0, %1, %2, %3;" : "=l"(d) : "l"(a), "l"(b), "l"(c)); return d;
}
__device__ __forceinline__ ull add2_(ull a, ull b) {
    ull d; asm("add.rn.f32x2 %0, %1, %2;" : "=l"(d) : "l"(a), "l"(b)); return d;
}
__device__ __forceinline__ ull pack2_(float lo, float hi) {
    ull d; asm("mov.b64 %0, {%1, %2};" : "=l"(d) : "f"(lo), "f"(hi)); return d;
}
__device__ __forceinline__ void unpack2_(ull v, float& lo, float& hi) {
    asm("mov.b64 {%0, %1}, %2;" : "=f"(lo), "=f"(hi) : "l"(v));
}

// One recurrence step. SLOT/BUF are literals -> ring stays in registers,
// shared buffers statically addressed. RENORM=1 on the first step of each
// 8-step group. Steps past n are frozen by predication (exact).
#define STEP(SLOT, BUF, RENORM) do {                                        \
    float ex_ = er##SLOT.x, ey_ = er##SLOT.y;                               \
    int tt_ = s0 + u + 4; if (tt_ > e) tt_ = e;                             \
    er##SLOT = ts2[(size_t)tt_ * 32 + tid];                                 \
    const bool gg_ = (u <= n);                                              \
    float c0_, c1_;                                                         \
    if (RENORM) {                                                           \
        float p0_ = __shfl_sync(FULL, Px, 0);                               \
        float Kp_ = lg2f_(p0_);                                             \
        c0_ = ex2f_(fmaf(ex_, INV_LN2, -Kp_));                              \
        c1_ = ex2f_(fmaf(ey_, INV_LN2, -Kp_));                              \
        Mcur += gg_ ? Kp_ : 0.0f;                                           \
    } else {                                                                \
        c0_ = ex2f_(ex_ * INV_LN2);                                         \
        c1_ = ex2f_(ey_ * INV_LN2);                                         \
    }                                                                       \
    __syncwarp();                                                           \
    const ulonglong2* p4_ = (const ulonglong2*)sp[w][BUF];                  \
    ull a0_=0, a1_=0, b0_=0, b1_=0;                                         \
    _Pragma("unroll")                                                       \
    for (int q = 0; q < 16; ++q) {                                          \
        ulonglong2 v_ = p4_[q];                                             \
        a0_ = fma2_(v_.x, EA[2*q],     a0_);                                \
        a1_ = fma2_(v_.y, EA[2*q + 1], a1_);                                \
        b0_ = fma2_(v_.x, EB[2*q],     b0_);                                \
        b1_ = fma2_(v_.y, EB[2*q + 1], b1_);                                \
    }                                                                       \
    float ax_, ay_, bx_, by_;                                               \
    unpack2_(add2_(a0_, a1_), ax_, ay_);                                    \
    unpack2_(add2_(b0_, b1_), bx_, by_);                                    \
    float nPx_ = (ax_ + ay_) * c0_;                                         \
    float nPy_ = (bx_ + by_) * c1_;                                         \
    Px = gg_ ? nPx_ : Px;  Py = gg_ ? nPy_ : Py;                            \
    ((float2*)sp[w][(BUF) ^ 1])[tid] = make_float2(Px, Py);                 \
    if (u == urec) { Msave = Mcur; Psave = Px; }                            \
    ++u;                                                                    \
} while (0)

// Fixed-time segmentation (seg k = times [64k, 64k+64)); seg k>0 restarts at
// s0 = max(0, e-80) (Birkhoff burn-in >= 16 steps); telescoping V-terms at
// the tau boundaries cancel the unknown restart shifts exactly.
__global__ __launch_bounds__(128, 2) void crf_loss_kernel(
    const float* __restrict__ ts,          // [B, S, L]
    const float* __restrict__ Tm,          // [L, L]
    const void*  __restrict__ labels_raw,  // [B, S] int32 or int64
    const void*  __restrict__ lengths_raw, // [B]    int32 or int64
    float* __restrict__ out)
{
    const int w   = threadIdx.x >> 5;
    const int tid = threadIdx.x & 31;            // lane: labels 2*tid, 2*tid+1
    const int seg = blockIdx.x >> 7;             // seg-major: full segs first
    const int b   = ((blockIdx.x & 127) << 2) + w;
    const unsigned FULL = 0xffffffffu;

    __shared__ __align__(16) float sp[4][2][LBL];

    const float INV_LN2 = 1.44269504088896340736f;
    const float LN2     = 0.69314718055994530942f;

    // dtype detect: lengths viewed as int32 — word[1]==0 iff data is int64
    const int* l32 = (const int*)lengths_raw;
    const bool is64 = (l32[1] == 0);
    int len;
    if (is64) len = (int)(((const long long*)lengths_raw)[b]);
    else      len = l32[b];

    const int  tauB   = seg * SEGW;
    const int  tauE   = tauB + SEGW;
    const bool active = (seg == 0) || (len > tauB);
    if (!active) return;
    const bool last = (len <= tauE);

    const float* tsb = ts + (size_t)b * SEQ * LBL;
    const float2* ts2 = (const float2*)tsb;

    // ---- E = exp(T) packed along i-pairs for this lane's two labels ----
    ull EA[32], EB[32];
    {
        const float2* Tm2 = (const float2*)Tm;
        #pragma unroll
        for (int q = 0; q < 32; ++q) {
            float2 r0 = Tm2[(2*q)     * 32 + tid];
            float2 r1 = Tm2[(2*q + 1) * 32 + tid];
            EA[q] = pack2_(__expf(r0.x), __expf(r1.x));
            EB[q] = pack2_(__expf(r0.y), __expf(r1.y));
        }
    }

    const int e  = last ? (len - 1) : tauE;
    int s0 = e - NSEG; if (seg == 0 || s0 < 0) s0 = 0;
    const int n  = e - s0;
    const int ng = (n + 7) >> 3;                  // groups of 8 (pad predicated)
    const int urec = (seg > 0) ? (tauB - s0) : -1;

    // ---- init A at s0 (true init iff s0==0) ----
    float2 a0v = ts2[(size_t)s0 * 32 + tid];
    float A0, A1;
    if (s0 == 0) {
        float2 tv = ((const float2*)(Tm + START_ID * LBL))[tid];
        A0 = (a0v.x + tv.x) * INV_LN2;
        A1 = (a0v.y + tv.y) * INV_LN2;
    } else {
        A0 = a0v.x * INV_LN2;
        A1 = a0v.y * INV_LN2;
    }
    float Mcur = __shfl_sync(FULL, A0, 0);
    float Px = ex2f_(A0 - Mcur);
    float Py = ex2f_(A1 - Mcur);
    ((float2*)sp[w][0])[tid] = make_float2(Px, Py);

    float Msave = Mcur, Psave = Px;

    // ---- named-register prefetch ring (no arrays, no dynamic indexing) ----
    float2 er0, er1, er2, er3;
    {
        int t1 = s0 + 1; if (t1 > e) t1 = e;
        int t2 = s0 + 2; if (t2 > e) t2 = e;
        int t3 = s0 + 3; if (t3 > e) t3 = e;
        int t4 = s0 + 4; if (t4 > e) t4 = e;
        er0 = ts2[(size_t)t1 * 32 + tid];
        er1 = ts2[(size_t)t2 * 32 + tid];
        er2 = ts2[(size_t)t3 * 32 + tid];
        er3 = ts2[(size_t)t4 * 32 + tid];
    }

    // ---- recurrence: ng groups of 8 fully static steps ----
    int u = 1;
    for (int g = 0; g < ng; ++g) {
        STEP(0, 0, 1); STEP(1, 1, 0); STEP(2, 0, 0); STEP(3, 1, 0);
        STEP(0, 0, 0); STEP(1, 1, 0); STEP(2, 0, 0); STEP(3, 1, 0);
    }

    // ---- segment contribution (log2 units) ----
    float fwd;
    if (last) {
        float tp0 = Tm[(2*tid)     * LBL + PAD_ID] * INV_LN2;
        float tp1 = Tm[(2*tid + 1) * LBL + PAD_ID] * INV_LN2;
        float z0 = Mcur + lg2f_(Px) + tp0;
        float z1 = Mcur + lg2f_(Py) + tp1;
        float m = fmaxf(z0, z1);
        #pragma unroll
        for (int o = 16; o > 0; o >>= 1)
            m = fmaxf(m, __shfl_xor_sync(FULL, m, o));
        float sv = ex2f_(z0 - m) + ex2f_(z1 - m);
        #pragma unroll
        for (int o = 16; o > 0; o >>= 1)
            sv += __shfl_xor_sync(FULL, sv, o);
        fwd = m + lg2f_(sv);
    } else {
        float pe0 = __shfl_sync(FULL, Px, 0);
        fwd = Mcur + lg2f_(pe0);                 // +V(tauE)
    }
    if (seg > 0) {
        float ps0 = __shfl_sync(FULL, Psave, 0);
        fwd -= (Msave + lg2f_(ps0));             // -V(tauB)
    }

    // ---- gold path score over [tauB, min(tauE, len)) ----
    const int hi = last ? len : tauE;
    float gsum = 0.0f;
    int last_label = 0;
    if (is64) {
        const long long* lab = (const long long*)labels_raw + (size_t)b * SEQ;
        for (int t = tauB + tid; t < hi; t += 32) {
            int lt = (int)lab[t];
            int pt = (t == 0) ? START_ID : (int)lab[t - 1];
            gsum += Tm[pt * LBL + lt] + tsb[(size_t)t * LBL + lt];
        }
        if (last && tid == 0) last_label = (int)lab[len - 1];
    } else {
        const int* lab = (const int*)labels_raw + (size_t)b * SEQ;
        for (int t = tauB + tid; t < hi; t += 32) {
            int lt = lab[t];
            int pt = (t == 0) ? START_ID : lab[t - 1];
            gsum += Tm[pt * LBL + lt] + tsb[(size_t)t * LBL + lt];
        }
        if (last && tid == 0) last_label = lab[len - 1];
    }
    #pragma unroll
    for (int o = 16; o > 0; o >>= 1)
        gsum += __shfl_xor_sync(FULL, gsum, o);

    if (tid == 0) {
        float gold = gsum + (last ? Tm[last_label * LBL + PAD_ID] : 0.0f);
        atomicAdd(out, (fwd * LN2 - gold) * (1.0f / (float)BATCH));
    }
}

extern "C" void kernel_launch(void* const* d_in, const int* in_sizes, int n_in,
                              void* d_out, int out_size)
{
    const float* ts      = (const float*)d_in[0];
    const float* Tm      = (const float*)d_in[1];
    const void*  labels  = d_in[2];
    const void*  lengths = d_in[3];
    float* out = (float*)d_out;

    cudaMemsetAsync(out, 0, sizeof(float));
    crf_loss_kernel<<<SEGS * (BATCH / 4), 128>>>(ts, Tm, labels, lengths, out);
}